// round 3
// baseline (speedup 1.0000x reference)
#include <cuda_runtime.h>

// FMREDynamicDropout: out = x * bernoulli_mask(threefry2x32, keep_prob[c])
// x: [32, 384, 56, 56] fp32, feature_importance: [384] fp32
//
// JAX >= 0.4.30 (threefry_partitionable = True) semantics:
//   key(42) -> (k0,k1) = (0, 42); ks2 = 0 ^ 42 ^ 0x1BD11BDA = 0x1BD11BF0
//   counts = iota(uint64, N); per element i: hash words (x0, x1) = (i>>32, i) = (0, i)
//   bits[i] = o0 ^ o1          (32-bit path XORs both threefry output words)
//   u = (bits >> 9) * 2^-23 (exact); mask = u < keep[c]
//     <=> (bits >> 9) < ceil(keep*2^23)  <=>  bits < (ceil(keep*2^23) << 9)

#define NCH   384
#define HW    3136u
#define NTOT  38535168u   // 32*384*56*56

__device__ unsigned g_thresh[NCH];   // pre-shifted: ceil(keep*2^23) << 9

// ---------------- prep: min/max over feature_importance, integer thresholds ----
__global__ void prep_kernel(const float* __restrict__ fi) {
    int t = threadIdx.x;            // 384 threads
    float v = fi[t];
    float mn = v, mx = v;
    #pragma unroll
    for (int o = 16; o > 0; o >>= 1) {
        mn = fminf(mn, __shfl_xor_sync(0xffffffffu, mn, o));
        mx = fmaxf(mx, __shfl_xor_sync(0xffffffffu, mx, o));
    }
    __shared__ float smn[12], smx[12];
    if ((t & 31) == 0) { smn[t >> 5] = mn; smx[t >> 5] = mx; }
    __syncthreads();
    if (t == 0) {
        float a = smn[0], b = smx[0];
        #pragma unroll
        for (int i = 1; i < 12; i++) { a = fminf(a, smn[i]); b = fmaxf(b, smx[i]); }
        smn[0] = a; smx[0] = b;
    }
    __syncthreads();
    float fmin = smn[0], fmax = smx[0];
    // match reference fp32 op ordering (no fma contraction)
    float scaled = __fdiv_rn(__fsub_rn(v, fmin), __fsub_rn(fmax, fmin));
    float rate   = __fadd_rn(0.1f, __fmul_rn(0.4f, __fsub_rn(1.0f, scaled)));
    float keep   = __fsub_rn(1.0f, rate);
    // u < keep  <=>  (bits>>9) < ceil(keep * 2^23)  <=>  bits < ceil(keep*2^23)<<9
    unsigned Tm = (unsigned)ceilf(__fmul_rn(keep, 8388608.0f));   // <= 0.9*2^23, no ovf
    g_thresh[t] = Tm << 9;
}

// ---------------- threefry2x32 with fixed key (0, 42), x0 = 0, x1 = i --------
__device__ __forceinline__ void tf_round(unsigned& x0, unsigned& x1, int r) {
    x0 += x1;
    x1 = __funnelshift_l(x1, x1, r);
    x1 ^= x0;
}

// returns o0 ^ o1 for counter words (0, i)
__device__ __forceinline__ unsigned tf_bits(unsigned i) {
    const unsigned ks0 = 0u, ks1 = 42u, ks2 = 0x1BD11BF0u;
    unsigned x0 = ks0;          // 0 + ks0
    unsigned x1 = i + ks1;
    tf_round(x0, x1, 13); tf_round(x0, x1, 15); tf_round(x0, x1, 26); tf_round(x0, x1, 6);
    x0 += ks1; x1 += ks2 + 1u;
    tf_round(x0, x1, 17); tf_round(x0, x1, 29); tf_round(x0, x1, 16); tf_round(x0, x1, 24);
    x0 += ks2; x1 += ks0 + 2u;
    tf_round(x0, x1, 13); tf_round(x0, x1, 15); tf_round(x0, x1, 26); tf_round(x0, x1, 6);
    x0 += ks0; x1 += ks1 + 3u;
    tf_round(x0, x1, 17); tf_round(x0, x1, 29); tf_round(x0, x1, 16); tf_round(x0, x1, 24);
    x0 += ks1; x1 += ks2 + 4u;
    tf_round(x0, x1, 13); tf_round(x0, x1, 15); tf_round(x0, x1, 26); tf_round(x0, x1, 6);
    x0 += ks2; x1 += ks0 + 5u;
    return x0 ^ x1;
}

// ---------------- main: 8 consecutive elements (two float4) per thread -------
__global__ void __launch_bounds__(256) drop_kernel(const float* __restrict__ x,
                                                   float* __restrict__ out) {
    unsigned j = (blockIdx.x * 256u + threadIdx.x) * 8u;   // j < NTOT, 8 | HW
    // all 8 elements share one channel (3136 % 8 == 0)
    unsigned T = g_thresh[(j / HW) % (unsigned)NCH];

    float4 a = *reinterpret_cast<const float4*>(x + j);
    float4 b = *reinterpret_cast<const float4*>(x + j + 4);

    unsigned m[8];
    #pragma unroll
    for (int k = 0; k < 8; k++)
        m[k] = tf_bits(j + (unsigned)k);

    float4 oa, ob;
    oa.x = (m[0] < T) ? a.x : 0.0f;
    oa.y = (m[1] < T) ? a.y : 0.0f;
    oa.z = (m[2] < T) ? a.z : 0.0f;
    oa.w = (m[3] < T) ? a.w : 0.0f;
    ob.x = (m[4] < T) ? b.x : 0.0f;
    ob.y = (m[5] < T) ? b.y : 0.0f;
    ob.z = (m[6] < T) ? b.z : 0.0f;
    ob.w = (m[7] < T) ? b.w : 0.0f;

    *reinterpret_cast<float4*>(out + j)     = oa;
    *reinterpret_cast<float4*>(out + j + 4) = ob;
}

extern "C" void kernel_launch(void* const* d_in, const int* in_sizes, int n_in,
                              void* d_out, int out_size) {
    const float* x  = (const float*)d_in[0];
    const float* fi = (const float*)d_in[1];
    if (n_in >= 2 && in_sizes[0] == NCH) {   // robust to input ordering
        x  = (const float*)d_in[1];
        fi = (const float*)d_in[0];
    }
    prep_kernel<<<1, NCH>>>(fi);
    // NTOT / 8 elems-per-thread / 256 threads = 18816 blocks, no remainder
    drop_kernel<<<18816, 256>>>(x, (float*)d_out);
}